// round 1
// baseline (speedup 1.0000x reference)
#include <cuda_runtime.h>
#include <cuda_bf16.h>

// Problem constants
#define BATCH 2
#define SEQ   2048
#define HID   1024
#define NH    16
#define HD    64
#define MROWS (BATCH * SEQ)   // 4096

// ---------------- scratch (device globals; no allocation allowed) -------
__device__ float g_h[MROWS * HID];
__device__ float g_q[MROWS * HID];
__device__ float g_k[MROWS * HID];
__device__ float g_v[MROWS * HID];
__device__ float g_ctx[MROWS * HID];

// ---------------- LayerNorm --------------------------------------------
__global__ void __launch_bounds__(256) ln_kernel(const float* __restrict__ X,
                                                 const float* __restrict__ gamma,
                                                 const float* __restrict__ beta,
                                                 float* __restrict__ Y) {
    int row = blockIdx.x;
    const float4* xr = (const float4*)(X + (size_t)row * HID);
    float4 v = xr[threadIdx.x];                    // 256 thr * 4 = 1024
    float s  = v.x + v.y + v.z + v.w;
    float ss = v.x*v.x + v.y*v.y + v.z*v.z + v.w*v.w;

    #pragma unroll
    for (int off = 16; off; off >>= 1) {
        s  += __shfl_xor_sync(0xffffffffu, s,  off);
        ss += __shfl_xor_sync(0xffffffffu, ss, off);
    }
    __shared__ float rs[8], rss[8];
    int w = threadIdx.x >> 5, ln = threadIdx.x & 31;
    if (ln == 0) { rs[w] = s; rss[w] = ss; }
    __syncthreads();
    float ts = 0.f, tss = 0.f;
    #pragma unroll
    for (int i = 0; i < 8; i++) { ts += rs[i]; tss += rss[i]; }
    float mu  = ts * (1.0f / HID);
    float var = tss * (1.0f / HID) - mu * mu;
    float inv = rsqrtf(var + 1e-12f);

    float4 g  = ((const float4*)gamma)[threadIdx.x];
    float4 be = ((const float4*)beta)[threadIdx.x];
    float4 r;
    r.x = (v.x - mu) * inv * g.x + be.x;
    r.y = (v.y - mu) * inv * g.y + be.y;
    r.z = (v.z - mu) * inv * g.z + be.z;
    r.w = (v.w - mu) * inv * g.w + be.w;
    ((float4*)(Y + (size_t)row * HID))[threadIdx.x] = r;
}

// ---------------- SGEMM:  C[m][n] = sum_k A[m][k]*B[n][k] + bias[n] -----
// A: [M,K] row-major, B: [N,K] row-major (i.e. C = A @ B^T + bias)
#define BM 128
#define BN 128
#define BKG 16
#define SPAD 132

__global__ void __launch_bounds__(256) sgemm_nt(const float* __restrict__ A,
                                                const float* __restrict__ B,
                                                const float* __restrict__ bias,
                                                float* __restrict__ C,
                                                int M, int N, int K) {
    __shared__ float As[BKG][SPAD];
    __shared__ float Bs[BKG][SPAD];
    int m0 = blockIdx.y * BM, n0 = blockIdx.x * BN;
    int tid = threadIdx.x;
    int tx = tid & 15, ty = tid >> 4;

    float c[8][8];
    #pragma unroll
    for (int i = 0; i < 8; i++)
        #pragma unroll
        for (int j = 0; j < 8; j++) c[i][j] = 0.f;

    const float* Ab = A + (size_t)m0 * K;
    const float* Bb = B + (size_t)n0 * K;

    for (int k0 = 0; k0 < K; k0 += BKG) {
        #pragma unroll
        for (int i = 0; i < 2; i++) {
            int id  = tid + i * 256;          // 0..511
            int row = id >> 2;
            int kq  = (id & 3) * 4;
            float4 va = *(const float4*)&Ab[(size_t)row * K + k0 + kq];
            As[kq + 0][row] = va.x; As[kq + 1][row] = va.y;
            As[kq + 2][row] = va.z; As[kq + 3][row] = va.w;
            float4 vb = *(const float4*)&Bb[(size_t)row * K + k0 + kq];
            Bs[kq + 0][row] = vb.x; Bs[kq + 1][row] = vb.y;
            Bs[kq + 2][row] = vb.z; Bs[kq + 3][row] = vb.w;
        }
        __syncthreads();

        #pragma unroll
        for (int k = 0; k < BKG; k++) {
            float4 a0 = *(float4*)&As[k][ty * 8];
            float4 a1 = *(float4*)&As[k][ty * 8 + 4];
            float4 b0 = *(float4*)&Bs[k][tx * 8];
            float4 b1 = *(float4*)&Bs[k][tx * 8 + 4];
            float a[8] = {a0.x, a0.y, a0.z, a0.w, a1.x, a1.y, a1.z, a1.w};
            float bb[8] = {b0.x, b0.y, b0.z, b0.w, b1.x, b1.y, b1.z, b1.w};
            #pragma unroll
            for (int i = 0; i < 8; i++)
                #pragma unroll
                for (int j = 0; j < 8; j++) c[i][j] += a[i] * bb[j];
        }
        __syncthreads();
    }

    float4 bi0 = *(const float4*)&bias[n0 + tx * 8];
    float4 bi1 = *(const float4*)&bias[n0 + tx * 8 + 4];
    #pragma unroll
    for (int i = 0; i < 8; i++) {
        int row = m0 + ty * 8 + i;
        float4 r0, r1;
        r0.x = c[i][0] + bi0.x; r0.y = c[i][1] + bi0.y;
        r0.z = c[i][2] + bi0.z; r0.w = c[i][3] + bi0.w;
        r1.x = c[i][4] + bi1.x; r1.y = c[i][5] + bi1.y;
        r1.z = c[i][6] + bi1.z; r1.w = c[i][7] + bi1.w;
        *(float4*)&C[(size_t)row * N + n0 + tx * 8]     = r0;
        *(float4*)&C[(size_t)row * N + n0 + tx * 8 + 4] = r1;
    }
}

// ---------------- Flash attention (fp32) --------------------------------
// Layout of q/k/v/ctx: [(b*SEQ + s)*HID + h*HD + d]
#define QT 128
#define KT 64
#define QSTR 132
#define KSTR 68
// smem floats: Qst 64*132 + KPs 64*132 + Vs 64*68 + mask 64
#define ATTN_SMEM_FLOATS (HD * QSTR + KT * QSTR + KT * KSTR + KT)
#define ATTN_SMEM_BYTES (ATTN_SMEM_FLOATS * 4)

__global__ void __launch_bounds__(256) attn_kernel(const float* __restrict__ Q,
                                                   const float* __restrict__ K,
                                                   const float* __restrict__ V,
                                                   const float* __restrict__ amask,
                                                   float* __restrict__ O) {
    extern __shared__ float sm[];
    float* Qst = sm;                      // [HD][QSTR]  (d-major, q contiguous)
    float* KPs = Qst + HD * QSTR;         // union: Kst [HD][KSTR] / Ps [KT][QSTR]
    float* Vs  = KPs + KT * QSTR;         // [KT][KSTR]
    float* msk = Vs + KT * KSTR;          // [KT]

    int b = blockIdx.z, hh = blockIdx.y;
    int q0 = blockIdx.x * QT;
    int tid = threadIdx.x;
    int tx = tid & 15, ty = tid >> 4;

    size_t rowbase = ((size_t)b * SEQ) * HID + hh * HD;

    // load Q tile transposed into smem
    for (int idx = tid; idx < QT * HD; idx += 256) {
        int s = idx >> 6, d = idx & 63;
        Qst[d * QSTR + s] = Q[rowbase + (size_t)(q0 + s) * HID + d];
    }

    float m_i[8], l_i[8], o[8][4];
    #pragma unroll
    for (int i = 0; i < 8; i++) {
        m_i[i] = -1e30f; l_i[i] = 0.f;
        #pragma unroll
        for (int dd = 0; dd < 4; dd++) o[i][dd] = 0.f;
    }

    for (int kk = 0; kk < SEQ; kk += KT) {
        __syncthreads();   // prev-iter PV readers done before overwrite
        for (int idx = tid; idx < KT * HD; idx += 256) {
            int s = idx >> 6, d = idx & 63;
            size_t g = rowbase + (size_t)(kk + s) * HID + d;
            KPs[d * KSTR + s] = K[g];
            Vs[s * KSTR + d]  = V[g];
        }
        if (tid < KT) msk[tid] = -1000.0f * (1.0f - amask[b * SEQ + kk + tid]);
        __syncthreads();

        // S = (Q K^T) * 0.125 + mask
        float sreg[8][4];
        #pragma unroll
        for (int i = 0; i < 8; i++)
            #pragma unroll
            for (int j = 0; j < 4; j++) sreg[i][j] = 0.f;

        #pragma unroll 4
        for (int d = 0; d < HD; d++) {
            float4 a0 = *(float4*)&Qst[d * QSTR + ty * 8];
            float4 a1 = *(float4*)&Qst[d * QSTR + ty * 8 + 4];
            float4 bq = *(float4*)&KPs[d * KSTR + tx * 4];
            float a[8] = {a0.x, a0.y, a0.z, a0.w, a1.x, a1.y, a1.z, a1.w};
            float bb[4] = {bq.x, bq.y, bq.z, bq.w};
            #pragma unroll
            for (int i = 0; i < 8; i++)
                #pragma unroll
                for (int j = 0; j < 4; j++) sreg[i][j] += a[i] * bb[j];
        }
        float mk[4];
        #pragma unroll
        for (int j = 0; j < 4; j++) mk[j] = msk[tx * 4 + j];

        __syncthreads();   // done reading Kst; about to overwrite as Ps

        #pragma unroll
        for (int i = 0; i < 8; i++) {
            float mt = -1e30f;
            #pragma unroll
            for (int j = 0; j < 4; j++) {
                sreg[i][j] = sreg[i][j] * 0.125f + mk[j];
                mt = fmaxf(mt, sreg[i][j]);
            }
            #pragma unroll
            for (int off = 8; off; off >>= 1)
                mt = fmaxf(mt, __shfl_xor_sync(0xffffffffu, mt, off));
            float mn = fmaxf(m_i[i], mt);
            float lt = 0.f;
            #pragma unroll
            for (int j = 0; j < 4; j++) {
                float p = __expf(sreg[i][j] - mn);
                sreg[i][j] = p;
                lt += p;
            }
            #pragma unroll
            for (int off = 8; off; off >>= 1)
                lt += __shfl_xor_sync(0xffffffffu, lt, off);
            float sc = __expf(m_i[i] - mn);
            l_i[i] = l_i[i] * sc + lt;
            m_i[i] = mn;
            #pragma unroll
            for (int dd = 0; dd < 4; dd++) o[i][dd] *= sc;
            #pragma unroll
            for (int j = 0; j < 4; j++)
                KPs[(tx * 4 + j) * QSTR + ty * 8 + i] = sreg[i][j];
        }
        __syncthreads();

        // O += P @ V
        #pragma unroll 4
        for (int kr = 0; kr < KT; kr++) {
            float4 p0 = *(float4*)&KPs[kr * QSTR + ty * 8];
            float4 p1 = *(float4*)&KPs[kr * QSTR + ty * 8 + 4];
            float4 vv = *(float4*)&Vs[kr * KSTR + tx * 4];
            float pq[8] = {p0.x, p0.y, p0.z, p0.w, p1.x, p1.y, p1.z, p1.w};
            float vb[4] = {vv.x, vv.y, vv.z, vv.w};
            #pragma unroll
            for (int i = 0; i < 8; i++)
                #pragma unroll
                for (int dd = 0; dd < 4; dd++) o[i][dd] += pq[i] * vb[dd];
        }
    }

    #pragma unroll
    for (int i = 0; i < 8; i++) {
        float inv = 1.0f / l_i[i];
        int s = q0 + ty * 8 + i;
        float4 r;
        r.x = o[i][0] * inv; r.y = o[i][1] * inv;
        r.z = o[i][2] * inv; r.w = o[i][3] * inv;
        *(float4*)&O[rowbase + (size_t)s * HID + tx * 4] = r;
    }
}

// ---------------- launch -------------------------------------------------
extern "C" void kernel_launch(void* const* d_in, const int* in_sizes, int n_in,
                              void* d_out, int out_size) {
    const float* hs    = (const float*)d_in[0];
    const float* amask = (const float*)d_in[1];
    const float* Wq    = (const float*)d_in[2];
    const float* bq    = (const float*)d_in[3];
    const float* Wk    = (const float*)d_in[4];
    const float* bk    = (const float*)d_in[5];
    const float* Wv    = (const float*)d_in[6];
    const float* bv    = (const float*)d_in[7];
    const float* Wd    = (const float*)d_in[8];
    const float* bd    = (const float*)d_in[9];
    const float* gamma = (const float*)d_in[10];
    const float* beta  = (const float*)d_in[11];
    float* out = (float*)d_out;

    float *h, *q, *k, *v, *ctx;
    cudaGetSymbolAddress((void**)&h,   g_h);
    cudaGetSymbolAddress((void**)&q,   g_q);
    cudaGetSymbolAddress((void**)&k,   g_k);
    cudaGetSymbolAddress((void**)&v,   g_v);
    cudaGetSymbolAddress((void**)&ctx, g_ctx);

    ln_kernel<<<MROWS, 256>>>(hs, gamma, beta, h);

    dim3 ggrid(HID / BN, MROWS / BM);   // (8, 32)
    sgemm_nt<<<ggrid, 256>>>(h, Wq, bq, q, MROWS, HID, HID);
    sgemm_nt<<<ggrid, 256>>>(h, Wk, bk, k, MROWS, HID, HID);
    sgemm_nt<<<ggrid, 256>>>(h, Wv, bv, v, MROWS, HID, HID);

    cudaFuncSetAttribute(attn_kernel, cudaFuncAttributeMaxDynamicSharedMemorySize,
                         ATTN_SMEM_BYTES);
    dim3 agrid(SEQ / QT, NH, BATCH);    // (16, 16, 2)
    attn_kernel<<<agrid, 256, ATTN_SMEM_BYTES>>>(q, k, v, amask, ctx);

    sgemm_nt<<<ggrid, 256>>>(ctx, Wd, bd, out, MROWS, HID, HID);
}